// round 3
// baseline (speedup 1.0000x reference)
#include <cuda_runtime.h>

// BambooBase fused Coulomb(Ewald) + D3-CSO dispersion edge kernel.
// R3: 2 edges/thread with 64-bit vectorized dense loads/stores (row/col int2,
// dij as 3x float2, all outputs as float2). Cuts stride-3 scalar line
// re-touching: dense L1 wavefronts drop ~3x, total wf/edge 2.97 -> 2.41.
// Gathers stay at the fundamental 2 random 16B loads per edge.

#define MAX_ATOMS 200064

__device__ float4 g_atom[MAX_ATOMS];

__global__ __launch_bounds__(256) void pack_atoms_kernel(
    const float* __restrict__ charge,
    const float* __restrict__ c6,
    const float* __restrict__ r0,
    int N)
{
    int i = blockIdx.x * blockDim.x + threadIdx.x;
    if (i >= N) return;
    const float SQRT_ELE = 18.222615f;   // sqrt(332.0637)
    float4 p;
    p.x = charge[i] * SQRT_ELE;
    p.y = sqrtf(c6[i]);
    p.z = 1.25f * r0[i];                 // so 2.5*r0ij = z_r + z_c
    p.w = 0.0f;
    g_atom[i] = p;
}

// Compute all 8 outputs for one edge.
__device__ __forceinline__ void edge_compute(
    const float4& pa, const float4& pb,
    float dx, float dy, float dz,
    float& ecoul, float& cfx, float& cfy, float& cfz,
    float& edisp, float& dfx, float& dfy, float& dfz)
{
    const float EWALD_F    = 1.12837917f;
    const float EWALD_P    = 0.3275911f;
    const float A0 = 0.254829592f, A1 = -0.284496736f, A2 = 1.421413741f,
                A3 = -1.453152027f, A4 = 1.061405429f;
    const float COUL_R0    = 2.2f;
    const float INV_R0     = 1.0f / 2.2f;
    const float BETA_OVER_R0 = 18.7f / 2.2f;   // 8.5
    const float INV_BETA   = 1.0f / 18.7f;
    const float G_EWALD    = 0.3f;
    const float R6_SHIFT   = 8303.765625f;      // 4.5^6
    const float INV_CUT6   = 1.0e-6f;           // 1/10^6

    float r2   = dx*dx + dy*dy + dz*dz;
    float rinv = rsqrtf(r2);
    float rij  = r2 * rinv;
    float rinv2 = rinv * rinv;

    // ---- Coulomb ----
    float prefactor = pa.x * pb.x * rinv;      // ELE folded into charges

    float x  = BETA_OVER_R0 * (rij - COUL_R0);
    float ex = __expf(x);
    float one_p_ex = 1.0f + ex;
    float inv_1pex = 1.0f / one_p_ex;
    float damp = ex * inv_1pex;                        // sigmoid(x)
    float sp   = __logf(one_p_ex) * INV_BETA;          // softplus
    float s    = rij * INV_R0 / (1.0f + sp);

    ecoul = prefactor * s;
    float fcoul = prefactor * damp * s * s;

    float grij  = G_EWALD * rij;
    float expm2 = __expf(-grij * grij);
    float t     = 1.0f / (1.0f + EWALD_P * grij);
    float erfc  = t * (A0 + t * (A1 + t * (A2 + t * (A3 + t * A4)))) * expm2;

    ecoul += prefactor * (erfc - 1.0f);
    fcoul += prefactor * (erfc + EWALD_F * grij * expm2 - 1.0f);

    float cscale = fcoul * rinv2;
    cfx = dx * cscale;
    cfy = dy * cscale;
    cfz = dz * cscale;

    // ---- Dispersion (D3-CSO) ----
    float c6ij = pa.y * pb.y;                   // sqrt(c6r*c6c)

    float r6pow = r2 * r2 * r2;
    float r6    = r6pow + R6_SHIFT;
    float inv_r6 = 1.0f / r6;

    float e   = __expf(rij - (pa.z + pb.z));    // rij - 2.5*r0ij
    float inv_1pe = 1.0f / (1.0f + e);
    float cso = 0.85f + 0.82f * inv_1pe;

    float c6_inv_r6 = c6ij * inv_r6;
    edisp = -c6_inv_r6 * cso;

    float r5 = r2 * r2 * rij;
    float fdisp = -6.0f * c6ij * r5 * inv_r6 * inv_r6 * cso
                  - c6_inv_r6 * (0.82f * e * inv_1pe * inv_1pe);

    float dscale = fdisp * rinv;
    dfx = dx * dscale;
    dfy = dy * dscale;
    dfz = dz * dscale;

    edisp += c6ij * INV_CUT6;
}

__global__ __launch_bounds__(256) void bamboo_edge_kernel2(
    const int2* __restrict__ row2,
    const int2* __restrict__ col2,
    const float2* __restrict__ dij2,
    float* __restrict__ out,
    int E)
{
    int t = blockIdx.x * blockDim.x + threadIdx.x;
    int nPairs = E >> 1;

    if (t < nPairs) {
        int2 rr = row2[t];
        int2 cc = col2[t];
        float2 da = dij2[3*t + 0];
        float2 db = dij2[3*t + 1];
        float2 dc = dij2[3*t + 2];

        float4 pa0 = g_atom[rr.x];
        float4 pb0 = g_atom[cc.x];
        float4 pa1 = g_atom[rr.y];
        float4 pb1 = g_atom[cc.y];

        float e0, c0x, c0y, c0z, ed0, d0x, d0y, d0z;
        float e1, c1x, c1y, c1z, ed1, d1x, d1y, d1z;
        edge_compute(pa0, pb0, da.x, da.y, db.x, e0, c0x, c0y, c0z, ed0, d0x, d0y, d0z);
        edge_compute(pa1, pb1, db.y, dc.x, dc.y, e1, c1x, c1y, c1z, ed1, d1x, d1y, d1z);

        long Eo = (long)E;
        float2* out_e  = (float2*)out;
        float2* out_cf = (float2*)(out + Eo);
        float2* out_ed = (float2*)(out + 4*Eo);
        float2* out_df = (float2*)(out + 5*Eo);

        out_e[t]       = make_float2(e0, e1);
        out_cf[3*t+0]  = make_float2(c0x, c0y);
        out_cf[3*t+1]  = make_float2(c0z, c1x);
        out_cf[3*t+2]  = make_float2(c1y, c1z);
        out_ed[t]      = make_float2(ed0, ed1);
        out_df[3*t+0]  = make_float2(d0x, d0y);
        out_df[3*t+1]  = make_float2(d0z, d1x);
        out_df[3*t+2]  = make_float2(d1y, d1z);
    }

    // Odd-E tail: last edge handled scalar by thread 0 of block 0.
    if ((E & 1) && t == 0) {
        int i = E - 1;
        const int*   row = (const int*)row2;
        const int*   col = (const int*)col2;
        const float* dij = (const float*)dij2;
        float4 pa = g_atom[row[i]];
        float4 pb = g_atom[col[i]];
        float e, cx, cy, cz, ed, dxo, dyo, dzo;
        edge_compute(pa, pb, dij[3*i], dij[3*i+1], dij[3*i+2],
                     e, cx, cy, cz, ed, dxo, dyo, dzo);
        long Eo = (long)E;
        out[i] = e;
        out[Eo + 3L*i + 0] = cx;
        out[Eo + 3L*i + 1] = cy;
        out[Eo + 3L*i + 2] = cz;
        out[4*Eo + i] = ed;
        out[5*Eo + 3L*i + 0] = dxo;
        out[5*Eo + 3L*i + 1] = dyo;
        out[5*Eo + 3L*i + 2] = dzo;
    }
}

extern "C" void kernel_launch(void* const* d_in, const int* in_sizes, int n_in,
                              void* d_out, int out_size)
{
    const int*   row    = (const int*)d_in[0];
    const int*   col    = (const int*)d_in[1];
    const float* dij    = (const float*)d_in[2];
    const float* charge = (const float*)d_in[3];
    const float* c6     = (const float*)d_in[4];
    const float* r0     = (const float*)d_in[5];
    float* out = (float*)d_out;

    int E = in_sizes[0];
    int N = in_sizes[3];

    int threads = 256;
    pack_atoms_kernel<<<(N + threads - 1) / threads, threads>>>(charge, c6, r0, N);

    int nPairs = (E >> 1);
    int work = nPairs > 0 ? nPairs : 1;
    bamboo_edge_kernel2<<<(work + threads - 1) / threads, threads>>>(
        (const int2*)row, (const int2*)col, (const float2*)dij, out, E);
}